// round 1
// baseline (speedup 1.0000x reference)
#include <cuda_runtime.h>

// Problem dims (4,4,32,256,256) fp32 -> BC=16 independent (b,ch) volumes of D*H*W
#define DD 32
#define HH 256
#define WW 256
#define TY 8
#define NROWS (TY + 2)   // 10 slab rows (tile + halo)
#define SLABW 260        // 258 used (x = -1..256), padded

__global__ __launch_bounds__(256)
void nms3d_kernel(const float* __restrict__ in, float* __restrict__ out) {
    __shared__ float slab[3][NROWS][SLABW];

    const int x  = threadIdx.x;            // 0..255
    const int y0 = blockIdx.x * TY;        // output rows y0..y0+7
    const int bc = blockIdx.y;             // 0..15

    const float* base  = in  + (size_t)bc * DD * HH * WW;
    float*       obase = out + (size_t)bc * DD * HH * WW;

    float m3v[3][NROWS];   // max over x-1..x+1 per (slot,row)
    float m2v[3][NROWS];   // max over {x-1, x+1}  per (slot,row)

    const bool xedge = (x == 0) || (x == WW - 1);

    // ---- load plane z into slot s, then compute separable row maxes ----
#define LOAD_PLANE(Z, S)                                                      \
    do {                                                                      \
        _Pragma("unroll")                                                     \
        for (int r = 0; r < NROWS; ++r) {                                     \
            int y = y0 - 1 + r;                                               \
            y = min(max(y, 0), HH - 1);                                       \
            float v = __ldg(base + ((size_t)(Z) * HH + y) * WW + x);          \
            slab[S][r][x + 1] = v;                                            \
            if (x == 0)      slab[S][r][0]      = v;                          \
            if (x == WW - 1) slab[S][r][WW + 1] = v;                          \
        }                                                                     \
    } while (0)

#define ROWMAX(S)                                                             \
    do {                                                                      \
        _Pragma("unroll")                                                     \
        for (int r = 0; r < NROWS; ++r) {                                     \
            float a = slab[S][r][x];                                          \
            float b = slab[S][r][x + 1];                                      \
            float c = slab[S][r][x + 2];                                      \
            m3v[S][r] = fmaxf(fmaxf(a, b), c);                                \
            m2v[S][r] = fmaxf(a, c);                                          \
        }                                                                     \
    } while (0)

    // ---- one z-step: bring in plane ZN (slot SN), emit outputs for ZN-1 ----
#define STEP(ZN, SP, SC, SN)                                                  \
    do {                                                                      \
        __syncthreads();  /* everyone done reading slot SN's old contents */  \
        LOAD_PLANE(ZN, SN);                                                   \
        __syncthreads();                                                      \
        ROWMAX(SN);                                                           \
        const int zo = (ZN) - 1;                                              \
        _Pragma("unroll")                                                     \
        for (int r = 1; r <= TY; ++r) {                                       \
            int y = y0 + r - 1;                                               \
            float c   = slab[SC][r][x + 1];                                   \
            float szp = fmaxf(fmaxf(m3v[SP][r - 1], m3v[SP][r]), m3v[SP][r + 1]); \
            float szn = fmaxf(fmaxf(m3v[SN][r - 1], m3v[SN][r]), m3v[SN][r + 1]); \
            float szc = fmaxf(fmaxf(m3v[SC][r - 1], m3v[SC][r + 1]), m2v[SC][r]); \
            float M   = fmaxf(fmaxf(szp, szn), szc);                          \
            bool edge = xedge || (y == 0) || (y == HH - 1);                   \
            float o   = (!edge && (c > M)) ? c : 0.0f;                        \
            obase[((size_t)zo * HH + y) * WW + x] = o;                        \
        }                                                                     \
    } while (0)

    // prologue: planes 0,1 into slots 0,1
    LOAD_PLANE(0, 0);
    LOAD_PLANE(1, 1);
    __syncthreads();
    ROWMAX(0);
    ROWMAX(1);

    // boundary plane z=0 is all zero
#pragma unroll
    for (int r = 0; r < TY; ++r)
        obase[(size_t)(y0 + r) * WW + x] = 0.0f;

    // main loop: zn = 2..31, slot rotation fully constant-indexed
#pragma unroll 1
    for (int t = 0; t < (DD - 2) / 3; ++t) {
        const int zn = 3 * t + 2;
        STEP(zn,     0, 1, 2);
        STEP(zn + 1, 1, 2, 0);
        STEP(zn + 2, 2, 0, 1);
    }

    // boundary plane z=D-1 is all zero
#pragma unroll
    for (int r = 0; r < TY; ++r)
        obase[((size_t)(DD - 1) * HH + y0 + r) * WW + x] = 0.0f;
}

extern "C" void kernel_launch(void* const* d_in, const int* in_sizes, int n_in,
                              void* d_out, int out_size) {
    const float* x = (const float*)d_in[0];
    float* out = (float*)d_out;
    (void)in_sizes; (void)n_in; (void)out_size;
    dim3 grid(HH / TY, 16);   // 32 y-tiles x 16 (b,ch) volumes = 512 blocks
    dim3 block(256);
    nms3d_kernel<<<grid, block>>>(x, out);
}

// round 2
// speedup vs baseline: 3.7950x; 3.7950x over previous
#include <cuda_runtime.h>

// dims (4,4,32,256,256) fp32 -> BC=16 volumes of D*H*W
#define DD 32
#define HH 256
#define WW 256
#define TY 4
#define NR (TY + 2)      // 6 slab rows (tile + y-halo)
#define ZT 8             // output planes per z-chunk (DD/4)
#define SLABW 260        // 258 used (x = -1..256), padded

__global__ __launch_bounds__(256, 4)
void nms3d_kernel(const float* __restrict__ in, float* __restrict__ out) {
    __shared__ float slab[3][NR][SLABW];

    const int x  = threadIdx.x;              // 0..255
    const int y0 = blockIdx.x * TY;          // output rows y0..y0+TY-1
    const int zc = blockIdx.y;               // 0..3 z-chunk
    const int bc = blockIdx.z;               // 0..15

    const float* base  = in  + (size_t)bc * DD * HH * WW;
    float*       obase = out + (size_t)bc * DD * HH * WW;
    const int z0 = zc * ZT;                  // first output plane of chunk

    float pref[NR];        // prefetched next plane (registers, LDG in flight)
    float m3v[3][NR];      // max over x-1..x+1 per (slot,row)
    float m2v[3][TY];      // max over {x-1,x+1}, interior rows only

    const bool xedge = (x == 0) || (x == WW - 1);

    // issue LDGs for plane Z (clamped) into pref registers
#define PREF(Z)                                                               \
    do {                                                                      \
        int zz = (Z); zz = min(max(zz, 0), DD - 1);                           \
        _Pragma("unroll")                                                     \
        for (int r = 0; r < NR; ++r) {                                        \
            int y = y0 - 1 + r; y = min(max(y, 0), HH - 1);                   \
            pref[r] = __ldg(base + ((size_t)zz * HH + y) * WW + x);           \
        }                                                                     \
    } while (0)

    // store pref regs into smem slot S (with x-halo replication)
#define COMMIT(S)                                                             \
    do {                                                                      \
        _Pragma("unroll")                                                     \
        for (int r = 0; r < NR; ++r) {                                        \
            slab[S][r][x + 1] = pref[r];                                      \
            if (x == 0)      slab[S][r][0]      = pref[r];                    \
            if (x == WW - 1) slab[S][r][WW + 1] = pref[r];                    \
        }                                                                     \
    } while (0)

    // separable x-maxes for slot S
#define ROWMAX(S)                                                             \
    do {                                                                      \
        _Pragma("unroll")                                                     \
        for (int r = 0; r < NR; ++r) {                                        \
            float a = slab[S][r][x];                                          \
            float b = slab[S][r][x + 1];                                      \
            float c = slab[S][r][x + 2];                                      \
            m3v[S][r] = fmaxf(fmaxf(a, b), c);                                \
            if (r >= 1 && r <= TY) m2v[S][r - 1] = fmaxf(a, c);               \
        }                                                                     \
    } while (0)

    // one z-step: commit prefetched plane (slot SN), prefetch next, emit zo=z0+i
#define STEP(i, SP, SC, SN)                                                   \
    do {                                                                      \
        __syncthreads();  /* readers of slot SN (step i-3) done */            \
        COMMIT(SN);                                                           \
        __syncthreads();                                                      \
        if ((i) + 1 < ZT) PREF(z0 + (i) + 2);  /* overlap with compute */     \
        ROWMAX(SN);                                                           \
        const int zo = z0 + (i);                                              \
        _Pragma("unroll")                                                     \
        for (int r = 1; r <= TY; ++r) {                                       \
            int y = y0 + r - 1;                                               \
            float c   = slab[SC][r][x + 1];                                   \
            float szp = fmaxf(fmaxf(m3v[SP][r - 1], m3v[SP][r]), m3v[SP][r + 1]); \
            float szn = fmaxf(fmaxf(m3v[SN][r - 1], m3v[SN][r]), m3v[SN][r + 1]); \
            float szc = fmaxf(fmaxf(m3v[SC][r - 1], m3v[SC][r + 1]), m2v[SC][r - 1]); \
            float M   = fmaxf(fmaxf(szp, szn), szc);                          \
            bool edge = xedge || (y == 0) || (y == HH - 1) ||                 \
                        (zo == 0) || (zo == DD - 1);                          \
            obase[((size_t)zo * HH + y) * WW + x] = (!edge && (c > M)) ? c : 0.0f; \
        }                                                                     \
    } while (0)

    // prologue: planes z0-1, z0 committed; z0+1 prefetch in flight
    PREF(z0 - 1); COMMIT(0);
    PREF(z0);     COMMIT(1);
    PREF(z0 + 1);
    __syncthreads();
    ROWMAX(0);
    ROWMAX(1);

    // 8 steps, slot rotation fully constant-indexed
    STEP(0, 0, 1, 2);
    STEP(1, 1, 2, 0);
    STEP(2, 2, 0, 1);
    STEP(3, 0, 1, 2);
    STEP(4, 1, 2, 0);
    STEP(5, 2, 0, 1);
    STEP(6, 0, 1, 2);
    STEP(7, 1, 2, 0);
}

extern "C" void kernel_launch(void* const* d_in, const int* in_sizes, int n_in,
                              void* d_out, int out_size) {
    const float* x = (const float*)d_in[0];
    float* out = (float*)d_out;
    (void)in_sizes; (void)n_in; (void)out_size;
    dim3 grid(HH / TY, DD / ZT, 16);   // 64 x 4 x 16 = 4096 blocks
    dim3 block(256);
    nms3d_kernel<<<grid, block>>>(x, out);
}

// round 3
// speedup vs baseline: 4.7506x; 1.2518x over previous
#include <cuda_runtime.h>

// dims (4,4,32,256,256) fp32 -> BC=16 volumes of D*H*W
#define DD 32
#define HH 256
#define WW 256
#define TY 4
#define NR (TY + 2)      // 6 slab rows (tile + y-halo)
#define ZT 8             // output planes per z-chunk
#define SLABW 264        // idx: data x at 4+x (4..259), halos at 3 and 260

__device__ __forceinline__ float2 f2max(float2 a, float2 b) {
    return make_float2(fmaxf(a.x, b.x), fmaxf(a.y, b.y));
}

__global__ __launch_bounds__(128, 5)
void nms3d_kernel(const float* __restrict__ in, float* __restrict__ out) {
    __shared__ float slab[3][NR][SLABW];

    const int t  = threadIdx.x;              // 0..127, handles x pair (2t, 2t+1)
    const int x0 = 2 * t;
    const int y0 = blockIdx.x * TY;
    const int zc = blockIdx.y;
    const int bc = blockIdx.z;

    const float* base  = in  + (size_t)bc * DD * HH * WW;
    float*       obase = out + (size_t)bc * DD * HH * WW;
    const int z0 = zc * ZT;

    float2 pref[NR];       // prefetched plane (pair per row)
    float2 m3[3][NR];      // 3-wide x-max per (slot,row), per position
    float2 m2[3][TY];      // {x-1,x+1} max, interior rows, per position

    const bool exa = (x0 == 0);
    const bool exb = (x0 + 1 == WW - 1);

    // issue LDG.64s for plane Z (clamped) into pref registers
#define PREF(Z)                                                               \
    do {                                                                      \
        int zz = (Z); zz = min(max(zz, 0), DD - 1);                           \
        _Pragma("unroll")                                                     \
        for (int r = 0; r < NR; ++r) {                                        \
            int y = y0 - 1 + r; y = min(max(y, 0), HH - 1);                   \
            pref[r] = __ldg((const float2*)(base + ((size_t)zz * HH + y) * WW + x0)); \
        }                                                                     \
    } while (0)

    // store pref into smem slot S (+ x-halo clamp values)
#define COMMIT(S)                                                             \
    do {                                                                      \
        _Pragma("unroll")                                                     \
        for (int r = 0; r < NR; ++r) {                                        \
            *(float2*)&slab[S][r][4 + x0] = pref[r];                          \
            if (exa) slab[S][r][3]   = pref[r].x;                             \
            if (exb) slab[S][r][260] = pref[r].y;                             \
        }                                                                     \
    } while (0)

    // separable x-maxes for slot S; w0,w1 come from pref registers (MUST run
    // before the next PREF overwrites them)
#define ROWMAX(S)                                                             \
    do {                                                                      \
        _Pragma("unroll")                                                     \
        for (int r = 0; r < NR; ++r) {                                        \
            float wm1 = slab[S][r][3 + x0];                                   \
            float w2  = slab[S][r][6 + x0];                                   \
            float w0  = pref[r].x, w1 = pref[r].y;                            \
            float mc  = fmaxf(w0, w1);                                        \
            m3[S][r].x = fmaxf(wm1, mc);                                      \
            m3[S][r].y = fmaxf(mc, w2);                                       \
            if (r >= 1 && r <= TY) {                                          \
                m2[S][r - 1].x = fmaxf(wm1, w1);                              \
                m2[S][r - 1].y = fmaxf(w0, w2);                               \
            }                                                                 \
        }                                                                     \
    } while (0)

    // one z-step: commit plane in pref (slot SN), rowmax it, prefetch next,
    // emit output plane zo = z0+i
#define STEP(i, SP, SC, SN)                                                   \
    do {                                                                      \
        __syncthreads();  /* readers of slot SN's old contents done */        \
        COMMIT(SN);                                                           \
        __syncthreads();                                                      \
        ROWMAX(SN);                                                           \
        if ((i) + 1 < ZT) PREF(z0 + (i) + 2);  /* LDGs overlap emit */        \
        const int zo = z0 + (i);                                              \
        const bool zed = (zo == 0) || (zo == DD - 1);                         \
        _Pragma("unroll")                                                     \
        for (int r = 1; r <= TY; ++r) {                                       \
            int y = y0 + r - 1;                                               \
            float2 c2  = *(const float2*)&slab[SC][r][4 + x0];                \
            float2 szp = f2max(f2max(m3[SP][r - 1], m3[SP][r]), m3[SP][r + 1]); \
            float2 szn = f2max(f2max(m3[SN][r - 1], m3[SN][r]), m3[SN][r + 1]); \
            float2 szc = f2max(f2max(m3[SC][r - 1], m3[SC][r + 1]), m2[SC][r - 1]); \
            float2 M   = f2max(f2max(szp, szn), szc);                         \
            bool ye = (y == 0) || (y == HH - 1) || zed;                       \
            float ox = (!ye && !exa && (c2.x > M.x)) ? c2.x : 0.0f;           \
            float oy = (!ye && !exb && (c2.y > M.y)) ? c2.y : 0.0f;           \
            *(float2*)(obase + ((size_t)zo * HH + y) * WW + x0) = make_float2(ox, oy); \
        }                                                                     \
    } while (0)

    // prologue: each plane committed + rowmaxed while its pref regs are live
    PREF(z0 - 1); COMMIT(0); __syncthreads(); ROWMAX(0);
    PREF(z0);     COMMIT(1); __syncthreads(); ROWMAX(1);
    PREF(z0 + 1);

    STEP(0, 0, 1, 2);
    STEP(1, 1, 2, 0);
    STEP(2, 2, 0, 1);
    STEP(3, 0, 1, 2);
    STEP(4, 1, 2, 0);
    STEP(5, 2, 0, 1);
    STEP(6, 0, 1, 2);
    STEP(7, 1, 2, 0);
}

extern "C" void kernel_launch(void* const* d_in, const int* in_sizes, int n_in,
                              void* d_out, int out_size) {
    const float* x = (const float*)d_in[0];
    float* out = (float*)d_out;
    (void)in_sizes; (void)n_in; (void)out_size;
    dim3 grid(HH / TY, DD / ZT, 16);   // 64 x 4 x 16 = 4096 blocks
    dim3 block(128);
    nms3d_kernel<<<grid, block>>>(x, out);
}